// round 13
// baseline (speedup 1.0000x reference)
#include <cuda_runtime.h>
#include <cuda_fp16.h>
#include <cstdint>

// ============================================================================
// GraphConvolution: out = (adj-premixed F) @ W^T + bias, fp16 MMA, fp32 accum.
// R13: M64 x N128 tile, 128 threads (4 warps, 2Mx2N, warp tile 32x64),
// 4 CTAs/SM -> 4 independent barrier domains per SM (de-synced pipelines).
// 2-stage cp.async B ring (issue-at-top, WAIT0), 2-slot A, quad-local premix,
// interleaved ldmatrix/MMA, XOR-hoisted addresses. N split: bx&1 -> W half;
// the pair shares F rows (L2 dedup).
// ============================================================================

#define KDIM    1024
#define NOUTD   256
#define MTILE   64
#define NHALFD  128
#define KC      64
#define NCHUNK  (KDIM / KC)          // 16
#define THREADS 128
#define ASLOT   (64 * 128)           // 8 KB per A slot
#define BSTAGE  (128 * 128)          // 16 KB per B stage (128 W rows)
#define SMEM_B0 (2 * ASLOT)          // 16384
#define SMEM_ADJ (SMEM_B0 + 2 * BSTAGE)  // 49152
#define SMEMB   (SMEM_ADJ + 64)          // 49216

__device__ __align__(16) __half WhalfG[NOUTD * KDIM];   // 512 KB scratch

// ---------------- helpers ----------------
__device__ __forceinline__ uint32_t smem_u32(const void* p) {
    uint32_t a;
    asm("{ .reg .u64 t; cvta.to.shared.u64 t, %1; cvt.u32.u64 %0, t; }" : "=r"(a) : "l"(p));
    return a;
}
__device__ __forceinline__ uint32_t swz(int row, int colbyte) {
    return (uint32_t)(row * 128 + (colbyte ^ ((row & 7) << 4)));
}
__device__ __forceinline__ void ldmatrix_x4(uint32_t& r0, uint32_t& r1,
                                            uint32_t& r2, uint32_t& r3, uint32_t addr) {
    asm volatile("ldmatrix.sync.aligned.m8n8.x4.shared.b16 {%0,%1,%2,%3}, [%4];"
                 : "=r"(r0), "=r"(r1), "=r"(r2), "=r"(r3) : "r"(addr));
}
__device__ __forceinline__ void mma16816(float* c, const uint32_t* a,
                                         uint32_t b0, uint32_t b1) {
    asm volatile("mma.sync.aligned.m16n8k16.row.col.f32.f16.f16.f32 "
                 "{%0,%1,%2,%3}, {%4,%5,%6,%7}, {%8,%9}, {%0,%1,%2,%3};"
                 : "+f"(c[0]), "+f"(c[1]), "+f"(c[2]), "+f"(c[3])
                 : "r"(a[0]), "r"(a[1]), "r"(a[2]), "r"(a[3]), "r"(b0), "r"(b1));
}
__device__ __forceinline__ uint32_t h2u(__half2 h) {
    return *reinterpret_cast<uint32_t*>(&h);
}
__device__ __forceinline__ void cp_async16(uint32_t dst, const void* src) {
    asm volatile("cp.async.cg.shared.global [%0], [%1], 16;" :: "r"(dst), "l"(src));
}
#define CP_COMMIT() asm volatile("cp.async.commit_group;" ::: "memory")
#define CP_WAIT0()  asm volatile("cp.async.wait_group 0;" ::: "memory")

// ---------------- kernel 1: W fp32 -> fp16 ----------------
__global__ void convW_kernel(const float* __restrict__ W) {
    int i = blockIdx.x * blockDim.x + threadIdx.x;        // 65536 threads, 4 f each
    float4 v = reinterpret_cast<const float4*>(W)[i];
    uint2 u = make_uint2(h2u(__floats2half2_rn(v.x, v.y)),
                         h2u(__floats2half2_rn(v.z, v.w)));
    reinterpret_cast<uint2*>(WhalfG)[i] = u;
}

// ---------------- kernel 2: fused premix + GEMM ----------------
__global__ void __launch_bounds__(THREADS, 4) gconv_gemm_kernel(
    const float* __restrict__ adj,   // [4,4]
    const float* __restrict__ F,     // [32768,1024]
    const float* __restrict__ bias,  // [256]
    float* __restrict__ out)         // [32768,256]
{
    extern __shared__ char smem[];
    const uint32_t sbase = smem_u32(smem);
    const int tid  = threadIdx.x;
    const int warp = tid >> 5;
    const int lane = tid & 31;
    const int wm   = warp & 1;       // 2 warps along M (32 rows each)
    const int wn   = warp >> 1;      // 2 warps along N (64 cols each)
    const int mtile = (int)(blockIdx.x >> 1);
    const int nhalf = (int)(blockIdx.x & 1);
    const size_t tile_row = (size_t)mtile * MTILE;

    // adj -> smem (saves 16 regs vs register copy; broadcast LDS in premix)
    if (tid < 16) ((float*)(smem + SMEM_ADJ))[tid] = __ldg(adj + tid);
    const float4* adj_s = (const float4*)(smem + SMEM_ADJ);

    float c[2][8][4];
#pragma unroll
    for (int i = 0; i < 2; i++)
#pragma unroll
        for (int j = 0; j < 8; j++)
#pragma unroll
            for (int k = 0; k < 4; k++) c[i][j][k] = 0.f;

    // A staging: quad = tid>>3 (rows 4q..4q+3), 8 K-cols per thread (2 passes)
    const int quad = tid >> 3;       // 0..15
    const int cs   = tid & 7;        // 0..7 -> cols cs*8 .. cs*8+7
    float4 ra[2][4];                 // [pass][row]

    const float* apBase = F + (tile_row + 4 * quad) * (size_t)KDIM + cs * 8;
    uint32_t soffA[4];               // p=0 offsets; p=1 = +8 (bit3, swizzle-safe)
#pragma unroll
    for (int n = 0; n < 4; n++) soffA[n] = swz(4 * quad + n, cs * 16);

    auto loadA = [&](int ch) {
        const float* ap = apBase + ch * KC;
#pragma unroll
        for (int p = 0; p < 2; p++)
#pragma unroll
            for (int m = 0; m < 4; m++)
                ra[p][m] = *reinterpret_cast<const float4*>(ap + p * 4 + (size_t)m * KDIM);
    };

    auto storeA = [&](int slot) {
        char* sa = smem + slot * ASLOT;
#pragma unroll
        for (int p = 0; p < 2; p++) {
#pragma unroll
            for (int n = 0; n < 4; n++) {
                const float4 an = adj_s[n];                  // LDS.128 broadcast
                float ox = an.x*ra[p][0].x + an.y*ra[p][1].x + an.z*ra[p][2].x + an.w*ra[p][3].x;
                float oy = an.x*ra[p][0].y + an.y*ra[p][1].y + an.z*ra[p][2].y + an.w*ra[p][3].y;
                float oz = an.x*ra[p][0].z + an.y*ra[p][1].z + an.z*ra[p][2].z + an.w*ra[p][3].z;
                float ow = an.x*ra[p][0].w + an.y*ra[p][1].w + an.z*ra[p][2].w + an.w*ra[p][3].w;
                uint2 u = make_uint2(h2u(__floats2half2_rn(ox, oy)),
                                     h2u(__floats2half2_rn(oz, ow)));
                *reinterpret_cast<uint2*>(sa + soffA[n] + p * 8) = u;
            }
        }
    };

    // B: cp.async fp16 W-half chunk into smem stage (128B per thread)
    const char* wBase = reinterpret_cast<const char*>(WhalfG)
                        + (size_t)nhalf * NHALFD * 2048;
    auto cpasyncB = [&](int ch, int stage) {
        const uint32_t bs = sbase + SMEM_B0 + stage * BSTAGE;
        const char* gbase = wBase + ch * 128;
#pragma unroll
        for (int i = 0; i < 8; i++) {
            const int u = tid + i * THREADS;     // 0..1023
            const int row = u >> 3;              // 0..127
            const int cb  = (u & 7) * 16;        // 0..112
            cp_async16(bs + swz(row, cb), gbase + (size_t)row * 2048 + cb);
        }
    };

    // XOR-hoisted ldmatrix offsets: addr(ks) = (base + off) ^ (ks<<5)
    const uint32_t aoff0 = swz(wm * 32 +  0 + (lane & 15), ((lane >> 4) & 1) * 16);
    const uint32_t aoff1 = swz(wm * 32 + 16 + (lane & 15), ((lane >> 4) & 1) * 16);
    const int brow = (lane & 7) + ((lane >> 4) & 1) * 8;
    const uint32_t bsel = ((lane >> 3) & 1) * 16;
    const uint32_t boff0 = swz(wn * 64 +  0 + brow, bsel);
    const uint32_t boff1 = swz(wn * 64 + 16 + brow, bsel);
    const uint32_t boff2 = swz(wn * 64 + 32 + brow, bsel);
    const uint32_t boff3 = swz(wn * 64 + 48 + brow, bsel);

    // ---- prologue ----
    cpasyncB(0, 0); CP_COMMIT();
    loadA(0);
    __syncthreads();                 // adj_s visible
    storeA(0);
    loadA(1);

    // ---- main loop ----
    for (int ch = 0; ch < NCHUNK; ch++) {
        CP_WAIT0();                 // B(ch) landed (only group outstanding)
        __syncthreads();            // A(ch) stored; MMA(ch-1) done everywhere

        // issue next B into the stage MMA(ch-1) just freed
        if (ch + 1 < NCHUNK) { cpasyncB(ch + 1, (ch + 1) & 1); CP_COMMIT(); }

        const uint32_t sa = sbase + (ch & 1) * ASLOT;
        const uint32_t sb = sbase + SMEM_B0 + (ch & 1) * BSTAGE;
#pragma unroll
        for (int ks = 0; ks < 4; ks++) {
            const uint32_t kx = (uint32_t)(ks << 5);
            uint32_t a[2][4];
            uint32_t b0[4], b1[4], b2[4], b3[4];
            ldmatrix_x4(b0[0], b0[1], b0[2], b0[3], (sb + boff0) ^ kx);
            ldmatrix_x4(a[0][0], a[0][1], a[0][2], a[0][3], (sa + aoff0) ^ kx);
            ldmatrix_x4(a[1][0], a[1][1], a[1][2], a[1][3], (sa + aoff1) ^ kx);
            ldmatrix_x4(b1[0], b1[1], b1[2], b1[3], (sb + boff1) ^ kx);
            mma16816(c[0][0], a[0], b0[0], b0[1]);
            mma16816(c[0][1], a[0], b0[2], b0[3]);
            mma16816(c[1][0], a[1], b0[0], b0[1]);
            mma16816(c[1][1], a[1], b0[2], b0[3]);
            ldmatrix_x4(b2[0], b2[1], b2[2], b2[3], (sb + boff2) ^ kx);
            mma16816(c[0][2], a[0], b1[0], b1[1]);
            mma16816(c[0][3], a[0], b1[2], b1[3]);
            mma16816(c[1][2], a[1], b1[0], b1[1]);
            mma16816(c[1][3], a[1], b1[2], b1[3]);
            ldmatrix_x4(b3[0], b3[1], b3[2], b3[3], (sb + boff3) ^ kx);
            mma16816(c[0][4], a[0], b2[0], b2[1]);
            mma16816(c[0][5], a[0], b2[2], b2[3]);
            mma16816(c[1][4], a[1], b2[0], b2[1]);
            mma16816(c[1][5], a[1], b2[2], b2[3]);
            mma16816(c[0][6], a[0], b3[0], b3[1]);
            mma16816(c[0][7], a[0], b3[2], b3[3]);
            mma16816(c[1][6], a[1], b3[0], b3[1]);
            mma16816(c[1][7], a[1], b3[2], b3[3]);
        }

        // premix + next-next A load AFTER the MMA block (tensor already running)
        if (ch + 1 < NCHUNK) storeA((ch + 1) & 1);  // slot free: MMA(ch-1) retired
        if (ch + 2 < NCHUNK) loadA(ch + 2);         // consumed after MMA(ch+1)
    }

    // ---- epilogue: + bias, store fp32 ----
    const int nbase = nhalf * NHALFD + wn * 64;
    float2 bb[8];
#pragma unroll
    for (int nf = 0; nf < 8; nf++)
        bb[nf] = *reinterpret_cast<const float2*>(bias + nbase + nf * 8 + (lane & 3) * 2);

#pragma unroll
    for (int mf = 0; mf < 2; mf++) {
#pragma unroll
        for (int nf = 0; nf < 8; nf++) {
            const size_t m = tile_row + wm * 32 + mf * 16 + (lane >> 2);
            const int n = nbase + nf * 8 + (lane & 3) * 2;
            float2 o0 = make_float2(c[mf][nf][0] + bb[nf].x, c[mf][nf][1] + bb[nf].y);
            float2 o1 = make_float2(c[mf][nf][2] + bb[nf].x, c[mf][nf][3] + bb[nf].y);
            *reinterpret_cast<float2*>(out + m * NOUTD + n) = o0;
            *reinterpret_cast<float2*>(out + (m + 8) * NOUTD + n) = o1;
        }
    }
}

// ============================================================================
extern "C" void kernel_launch(void* const* d_in, const int* in_sizes, int n_in,
                              void* d_out, int out_size) {
    (void)in_sizes; (void)n_in; (void)out_size;
    const float* adj  = (const float*)d_in[0];   // [4,4]
    const float* F    = (const float*)d_in[1];   // [8192,4,1024]
    const float* W    = (const float*)d_in[2];   // [256,1024]
    const float* bias = (const float*)d_in[3];   // [256]
    float* out = (float*)d_out;                  // [8192,4,256]

    convW_kernel<<<256, 256>>>(W);

    cudaFuncSetAttribute(gconv_gemm_kernel,
                         cudaFuncAttributeMaxDynamicSharedMemorySize, SMEMB);
    gconv_gemm_kernel<<<(32768 / MTILE) * 2, THREADS, SMEMB>>>(adj, F, bias, out);
}

// round 14
// speedup vs baseline: 1.7138x; 1.7138x over previous
#include <cuda_runtime.h>
#include <cuda_fp16.h>
#include <cstdint>

// ============================================================================
// GraphConvolution: out = (adj-premixed F) @ W^T + bias, fp16 MMA, fp32 accum.
// R14 = R10 (best: 69.95us) + loop-invariant address hoisting ONLY
// (deconfounded from R12's harmful CTA de-phasing; K-order kept natural so
// co-resident CTAs share W chunks in L2).
// 256-thread CTA (M64 x N256), 2 CTAs/SM, cp.async 3-stage B ring,
// zero-shfl quad-local premix, interleaved ldmatrix/MMA. Warp tile 32x64.
// ============================================================================

#define KDIM    1024
#define NOUTD   256
#define MTILE   64
#define KC      64
#define NCHUNK  (KDIM / KC)          // 16
#define THREADS 256
#define ASLOT   (64 * 128)           // 8 KB per A slot (fp16, 128B rows)
#define BSTAGE  (256 * 128)          // 32 KB per B stage
#define SMEM_B0 (2 * ASLOT)          // 16384
#define SMEMB   (SMEM_B0 + 3 * BSTAGE)  // 114688 = 112 KB

__device__ __align__(16) __half WhalfG[NOUTD * KDIM];   // 512 KB scratch

// ---------------- helpers ----------------
__device__ __forceinline__ uint32_t smem_u32(const void* p) {
    uint32_t a;
    asm("{ .reg .u64 t; cvta.to.shared.u64 t, %1; cvt.u32.u64 %0, t; }" : "=r"(a) : "l"(p));
    return a;
}
__device__ __forceinline__ uint32_t swz(int row, int colbyte) {
    return (uint32_t)(row * 128 + (colbyte ^ ((row & 7) << 4)));
}
__device__ __forceinline__ void ldmatrix_x4(uint32_t& r0, uint32_t& r1,
                                            uint32_t& r2, uint32_t& r3, uint32_t addr) {
    asm volatile("ldmatrix.sync.aligned.m8n8.x4.shared.b16 {%0,%1,%2,%3}, [%4];"
                 : "=r"(r0), "=r"(r1), "=r"(r2), "=r"(r3) : "r"(addr));
}
__device__ __forceinline__ void mma16816(float* c, const uint32_t* a,
                                         uint32_t b0, uint32_t b1) {
    asm volatile("mma.sync.aligned.m16n8k16.row.col.f32.f16.f16.f32 "
                 "{%0,%1,%2,%3}, {%4,%5,%6,%7}, {%8,%9}, {%0,%1,%2,%3};"
                 : "+f"(c[0]), "+f"(c[1]), "+f"(c[2]), "+f"(c[3])
                 : "r"(a[0]), "r"(a[1]), "r"(a[2]), "r"(a[3]), "r"(b0), "r"(b1));
}
__device__ __forceinline__ uint32_t h2u(__half2 h) {
    return *reinterpret_cast<uint32_t*>(&h);
}
__device__ __forceinline__ void cp_async16(uint32_t dst, const void* src) {
    asm volatile("cp.async.cg.shared.global [%0], [%1], 16;" :: "r"(dst), "l"(src));
}
#define CP_COMMIT() asm volatile("cp.async.commit_group;" ::: "memory")
#define CP_WAIT1()  asm volatile("cp.async.wait_group 1;" ::: "memory")

// ---------------- kernel 1: W fp32 -> fp16 ----------------
__global__ void convW_kernel(const float* __restrict__ W) {
    int i = blockIdx.x * blockDim.x + threadIdx.x;        // 65536 threads, 4 f each
    float4 v = reinterpret_cast<const float4*>(W)[i];
    uint2 u = make_uint2(h2u(__floats2half2_rn(v.x, v.y)),
                         h2u(__floats2half2_rn(v.z, v.w)));
    reinterpret_cast<uint2*>(WhalfG)[i] = u;
}

// ---------------- kernel 2: fused premix + GEMM ----------------
__global__ void __launch_bounds__(THREADS, 2) gconv_gemm_kernel(
    const float* __restrict__ adj,   // [4,4]
    const float* __restrict__ F,     // [32768,1024]
    const float* __restrict__ bias,  // [256]
    float* __restrict__ out)         // [32768,256]
{
    extern __shared__ char smem[];
    const uint32_t sbase = smem_u32(smem);
    const int tid  = threadIdx.x;
    const int warp = tid >> 5;
    const int lane = tid & 31;
    const int wm   = warp & 1;       // 2 warps along M
    const int wn   = warp >> 1;      // 4 warps along N
    const size_t tile_row = (size_t)blockIdx.x * MTILE;

    // Full adj matrix per thread (local zero-shfl premix)
    const float4 A0 = __ldg((const float4*)(adj + 0));
    const float4 A1 = __ldg((const float4*)(adj + 4));
    const float4 A2 = __ldg((const float4*)(adj + 8));
    const float4 A3 = __ldg((const float4*)(adj + 12));

    float c[2][8][4];
#pragma unroll
    for (int i = 0; i < 2; i++)
#pragma unroll
        for (int j = 0; j < 8; j++)
#pragma unroll
            for (int k = 0; k < 4; k++) c[i][j][k] = 0.f;

    // A staging: 4 source rows x 4 cols (quad-local premix)
    const int quad = tid >> 4;       // 0..15  -> rows 4*quad .. 4*quad+3
    const int cg   = tid & 15;       // 0..15  -> cols cg*4 .. cg*4+3
    float4 ra[4];

    // ---- loop-invariant addresses (hoisted once) ----
    const float* apBase = F + (tile_row + 4 * quad) * (size_t)KDIM + cg * 4;
    uint32_t soffA[4];               // storeA smem offsets
#pragma unroll
    for (int n = 0; n < 4; n++) soffA[n] = swz(4 * quad + n, cg * 8);
    uint32_t boffS[8];               // cp.async smem dst offsets
    uint32_t boffG[8];               // cp.async gmem row-byte offsets
#pragma unroll
    for (int i = 0; i < 8; i++) {
        const int u = tid + i * THREADS;     // 0..2047
        const int row = u >> 3;              // 0..255
        const int cb  = (u & 7) * 16;        // 0..112
        boffS[i] = swz(row, cb);
        boffG[i] = (uint32_t)(row * 2048 + cb);
    }

    auto loadA = [&](int ch) {
        const float* ap = apBase + ch * KC;
#pragma unroll
        for (int m = 0; m < 4; m++)
            ra[m] = *reinterpret_cast<const float4*>(ap + (size_t)m * KDIM);
    };

    auto storeA = [&](int slot) {
        char* sa = smem + slot * ASLOT;
#pragma unroll
        for (int n = 0; n < 4; n++) {
            const float4 an = (n == 0) ? A0 : (n == 1) ? A1 : (n == 2) ? A2 : A3;
            float ox = an.x * ra[0].x + an.y * ra[1].x + an.z * ra[2].x + an.w * ra[3].x;
            float oy = an.x * ra[0].y + an.y * ra[1].y + an.z * ra[2].y + an.w * ra[3].y;
            float oz = an.x * ra[0].z + an.y * ra[1].z + an.z * ra[2].z + an.w * ra[3].z;
            float ow = an.x * ra[0].w + an.y * ra[1].w + an.z * ra[2].w + an.w * ra[3].w;
            uint2 u = make_uint2(h2u(__floats2half2_rn(ox, oy)),
                                 h2u(__floats2half2_rn(oz, ow)));
            *reinterpret_cast<uint2*>(sa + soffA[n]) = u;
        }
    };

    auto cpasyncB = [&](int ch, int stage) {
        const uint32_t bs = sbase + SMEM_B0 + stage * BSTAGE;
        const char* gbase = reinterpret_cast<const char*>(WhalfG) + ch * 128;
#pragma unroll
        for (int i = 0; i < 8; i++)
            cp_async16(bs + boffS[i], gbase + boffG[i]);
    };

    // XOR-hoisted ldmatrix offsets: addr(ks) = (base + off) ^ (ks<<5)
    const uint32_t aoff0 = swz(wm * 32 +  0 + (lane & 15), ((lane >> 4) & 1) * 16);
    const uint32_t aoff1 = swz(wm * 32 + 16 + (lane & 15), ((lane >> 4) & 1) * 16);
    const int brow = (lane & 7) + ((lane >> 4) & 1) * 8;
    const uint32_t bsel = ((lane >> 3) & 1) * 16;
    const uint32_t boff0 = swz(wn * 64 +  0 + brow, bsel);
    const uint32_t boff1 = swz(wn * 64 + 16 + brow, bsel);
    const uint32_t boff2 = swz(wn * 64 + 32 + brow, bsel);
    const uint32_t boff3 = swz(wn * 64 + 48 + brow, bsel);

    // ---- prologue ----
    cpasyncB(0, 0); CP_COMMIT();
    cpasyncB(1, 1); CP_COMMIT();
    loadA(0); storeA(0);
    loadA(1);

    // ---- main loop (MMA-first; premix/loads in the tensor shadow) ----
    for (int ch = 0; ch < NCHUNK; ch++) {
        CP_WAIT1();                 // B(ch) arrived (B(ch+1) may be in flight)
        __syncthreads();            // A(ch) visible; MMA(ch-1) done everywhere

        if (ch + 2 < NCHUNK) cpasyncB(ch + 2, (ch + 2) % 3);
        CP_COMMIT();                // commit every iter -> constant wait depth

        const uint32_t sa = sbase + (ch & 1) * ASLOT;
        const uint32_t sb = sbase + SMEM_B0 + (ch % 3) * BSTAGE;
#pragma unroll
        for (int ks = 0; ks < 4; ks++) {
            const uint32_t kx = (uint32_t)(ks << 5);
            uint32_t a[2][4];
            uint32_t b0[4], b1[4], b2[4], b3[4];
            ldmatrix_x4(b0[0], b0[1], b0[2], b0[3], (sb + boff0) ^ kx);
            ldmatrix_x4(a[0][0], a[0][1], a[0][2], a[0][3], (sa + aoff0) ^ kx);
            ldmatrix_x4(a[1][0], a[1][1], a[1][2], a[1][3], (sa + aoff1) ^ kx);
            ldmatrix_x4(b1[0], b1[1], b1[2], b1[3], (sb + boff1) ^ kx);
            mma16816(c[0][0], a[0], b0[0], b0[1]);
            mma16816(c[0][1], a[0], b0[2], b0[3]);
            mma16816(c[1][0], a[1], b0[0], b0[1]);
            mma16816(c[1][1], a[1], b0[2], b0[3]);
            ldmatrix_x4(b2[0], b2[1], b2[2], b2[3], (sb + boff2) ^ kx);
            mma16816(c[0][2], a[0], b1[0], b1[1]);
            mma16816(c[0][3], a[0], b1[2], b1[3]);
            mma16816(c[1][2], a[1], b1[0], b1[1]);
            mma16816(c[1][3], a[1], b1[2], b1[3]);
            ldmatrix_x4(b3[0], b3[1], b3[2], b3[3], (sb + boff3) ^ kx);
            mma16816(c[0][4], a[0], b2[0], b2[1]);
            mma16816(c[0][5], a[0], b2[2], b2[3]);
            mma16816(c[1][4], a[1], b2[0], b2[1]);
            mma16816(c[1][5], a[1], b2[2], b2[3]);
            mma16816(c[0][6], a[0], b3[0], b3[1]);
            mma16816(c[0][7], a[0], b3[2], b3[3]);
            mma16816(c[1][6], a[1], b3[0], b3[1]);
            mma16816(c[1][7], a[1], b3[2], b3[3]);
        }

        // premix + next-next A load AFTER the MMA block (tensor already running)
        if (ch + 1 < NCHUNK) storeA((ch + 1) & 1);  // slot free: MMA(ch-1) retired
        if (ch + 2 < NCHUNK) loadA(ch + 2);         // consumed after MMA(ch+1)
    }

    // ---- epilogue: + bias, store fp32 ----
    float2 bb[8];
#pragma unroll
    for (int nf = 0; nf < 8; nf++)
        bb[nf] = *reinterpret_cast<const float2*>(bias + wn * 64 + nf * 8 + (lane & 3) * 2);

#pragma unroll
    for (int mf = 0; mf < 2; mf++) {
#pragma unroll
        for (int nf = 0; nf < 8; nf++) {
            const size_t m = tile_row + wm * 32 + mf * 16 + (lane >> 2);
            const int n = wn * 64 + nf * 8 + (lane & 3) * 2;
            float2 o0 = make_float2(c[mf][nf][0] + bb[nf].x, c[mf][nf][1] + bb[nf].y);
            float2 o1 = make_float2(c[mf][nf][2] + bb[nf].x, c[mf][nf][3] + bb[nf].y);
            *reinterpret_cast<float2*>(out + m * NOUTD + n) = o0;
            *reinterpret_cast<float2*>(out + (m + 8) * NOUTD + n) = o1;
        }
    }
}

// ============================================================================
extern "C" void kernel_launch(void* const* d_in, const int* in_sizes, int n_in,
                              void* d_out, int out_size) {
    (void)in_sizes; (void)n_in; (void)out_size;
    const float* adj  = (const float*)d_in[0];   // [4,4]
    const float* F    = (const float*)d_in[1];   // [8192,4,1024]
    const float* W    = (const float*)d_in[2];   // [256,1024]
    const float* bias = (const float*)d_in[3];   // [256]
    float* out = (float*)d_out;                  // [8192,4,256]

    convW_kernel<<<256, 256>>>(W);

    cudaFuncSetAttribute(gconv_gemm_kernel,
                         cudaFuncAttributeMaxDynamicSharedMemorySize, SMEMB);
    gconv_gemm_kernel<<<32768 / MTILE, THREADS, SMEMB>>>(adj, F, bias, out);
}